// round 8
// baseline (speedup 1.0000x reference)
#include <cuda_runtime.h>
#include <cuda_bf16.h>
#include <cstdint>
#include <math.h>

#define C_DIM 320
#define B_DIM 8
#define T_TOP 2048
#define NDIV 11.0

// ---------------- scratch ----------------
#define POOL_FLOATS (B_DIM * C_DIM * 2047)
#define X_ELEMS (B_DIM * C_DIM * 8190)
__device__ float g_z1p[POOL_FLOATS];
__device__ float g_z2p[POOL_FLOATS];
__device__ __align__(256) __nv_bfloat16 g_xhi[X_ELEMS];
__device__ double g_acc[2];   // [0]=inst, [1]=temp

// ---------------- PTX helpers (sm_80-era only) ----------------
__device__ __forceinline__ uint32_t smem_u32(const void* p) {
    uint32_t a;
    asm("{ .reg .u64 t; cvta.to.shared.u64 t, %1; cvt.u32.u64 %0, t; }" : "=r"(a) : "l"(p));
    return a;
}
__device__ __forceinline__ void ldmx4(uint32_t* r, uint32_t addr) {
    asm volatile("ldmatrix.sync.aligned.m8n8.x4.shared.b16 {%0,%1,%2,%3}, [%4];"
                 : "=r"(r[0]), "=r"(r[1]), "=r"(r[2]), "=r"(r[3]) : "r"(addr));
}
__device__ __forceinline__ void mma_bf16(float* c, const uint32_t* a,
                                         uint32_t b0, uint32_t b1) {
    asm volatile("mma.sync.aligned.m16n8k16.row.col.f32.bf16.bf16.f32 "
                 "{%0,%1,%2,%3}, {%4,%5,%6,%7}, {%8,%9}, {%0,%1,%2,%3};"
                 : "+f"(c[0]), "+f"(c[1]), "+f"(c[2]), "+f"(c[3])
                 : "r"(a[0]), "r"(a[1]), "r"(a[2]), "r"(a[3]), "r"(b0), "r"(b1));
}
__device__ __forceinline__ void cpa16(uint32_t dst, const void* src, bool valid) {
    int sz = valid ? 16 : 0;
    asm volatile("cp.async.cg.shared.global [%0], [%1], 16, %2;"
                 :: "r"(dst), "l"(src), "r"(sz));
}
#define CP_COMMIT() asm volatile("cp.async.commit_group;" ::: "memory")
#define CP_WAIT0()  asm volatile("cp.async.wait_group 0;" ::: "memory")

// ---------------- trivial kernels ----------------
__global__ void zero_kernel() { g_acc[0] = 0.0; g_acc[1] = 0.0; }

__global__ void fin_kernel(float* out) {
    double inst = g_acc[0] / NDIV;
    double temp = g_acc[1] / NDIV;
    out[0] = (float)(0.5 * inst + 0.5 * temp);
    out[1] = (float)inst;
    out[2] = (float)temp;
}

// convert level-0 to bf16, layout [b][row(2T)][c]
__global__ void convert_kernel(const float* __restrict__ z1, const float* __restrict__ z2,
                               int T, long xoff) {
    __shared__ float tile[32][33];
    int zsel = blockIdx.z & 1;
    int b = blockIdx.z >> 1;
    const float* src = (zsel ? z2 : z1) + (long)b * C_DIM * T;
    int t0 = blockIdx.x * 32, c0 = blockIdx.y * 32;
    int tx = threadIdx.x, ty = threadIdx.y;   // 32 x 8
#pragma unroll
    for (int j = 0; j < 4; j++) {
        int c = c0 + ty + 8 * j;
        int t = t0 + tx;
        tile[ty + 8 * j][tx] = (t < T) ? src[(long)c * T + t] : 0.f;
    }
    __syncthreads();
    long R = 2L * T;
#pragma unroll
    for (int j = 0; j < 4; j++) {
        int row = t0 + ty + 8 * j;
        int c = c0 + tx;
        if (row < T) {
            float x = tile[tx][ty + 8 * j];
            long grow = zsel ? (T + row) : row;
            g_xhi[xoff + ((long)b * R + grow) * C_DIM + c] = __float2bfloat16(x);
        }
    }
}

// fused pool (2:1 max) + convert for levels >= 1
__global__ void poolconv_kernel(const float* __restrict__ s1, const float* __restrict__ s2,
                                float* __restrict__ d1, float* __restrict__ d2,
                                int T, long xoff) {
    __shared__ float tile[32][33];
    int zsel = blockIdx.z & 1;
    int b = blockIdx.z >> 1;
    int Tin = 2 * T;
    const float* src = (zsel ? s2 : s1) + (long)b * C_DIM * Tin;
    float* dst = (zsel ? d2 : d1) + (long)b * C_DIM * T;
    int t0 = blockIdx.x * 32, c0 = blockIdx.y * 32;
    int tx = threadIdx.x, ty = threadIdx.y;
#pragma unroll
    for (int j = 0; j < 4; j++) {
        int c = c0 + ty + 8 * j;
        int t = t0 + tx;
        float v = 0.f;
        if (t < T) {
            v = fmaxf(src[(long)c * Tin + 2 * t], src[(long)c * Tin + 2 * t + 1]);
            dst[(long)c * T + t] = v;
        }
        tile[ty + 8 * j][tx] = v;
    }
    __syncthreads();
    long R = 2L * T;
#pragma unroll
    for (int j = 0; j < 4; j++) {
        int row = t0 + ty + 8 * j;
        int c = c0 + tx;
        if (row < T) {
            float x = tile[tx][ty + 8 * j];
            long grow = zsel ? (T + row) : row;
            g_xhi[xoff + ((long)b * R + grow) * C_DIM + c] = __float2bfloat16(x);
        }
    }
}

// ---------------- instance loss, all levels in one launch ----------------
__global__ void inst_all_kernel(const float* __restrict__ z1, const float* __restrict__ z2) {
    __shared__ float sm[16][8][64];
    int rem = blockIdx.x;
    int T = T_TOP;
    int lvl = 0;
    while (true) {
        int nb = (T + 63) >> 6;
        if (rem < nb) break;
        rem -= nb;
        T >>= 1;
        lvl++;
    }
    const float *s1, *s2;
    if (lvl == 0) { s1 = z1; s2 = z2; }
    else {
        long off = (long)B_DIM * C_DIM * (T_TOP - 2 * T);
        s1 = g_z1p + off; s2 = g_z2p + off;
    }
    double scale = 1.0 / (16.0 * (double)T);

    int tid  = threadIdx.x;
    int lane = tid & 31;
    int grp  = tid >> 5;
    int t0   = rem * 64;
    int row0 = grp * 2, row1 = row0 + 1;

    float a0x[16], a0y[16], a1x[16], a1y[16];
#pragma unroll
    for (int m = 0; m < 16; m++) { a0x[m] = a0y[m] = a1x[m] = a1y[m] = 0.f; }

    for (int cc = 0; cc < C_DIM; cc += 8) {
        __syncthreads();
        for (int e = tid; e < 16 * 8 * 64; e += 256) {
            int t = e & 63, c = (e >> 6) & 7, v = e >> 9;
            int gt = t0 + t;
            float val = 0.f;
            if (gt < T) {
                int gc = cc + c;
                val = (v < 8) ? s1[((long)v * C_DIM + gc) * T + gt]
                              : s2[((long)(v - 8) * C_DIM + gc) * T + gt];
            }
            sm[v][c][t] = val;
        }
        __syncthreads();
#pragma unroll
        for (int c = 0; c < 8; c++) {
            float2 x0 = *reinterpret_cast<const float2*>(&sm[row0][c][2 * lane]);
            float2 x1 = *reinterpret_cast<const float2*>(&sm[row1][c][2 * lane]);
#pragma unroll
            for (int m = 0; m < 16; m++) {
                float2 y = *reinterpret_cast<const float2*>(&sm[m][c][2 * lane]);
                a0x[m] += x0.x * y.x; a0y[m] += x0.y * y.y;
                a1x[m] += x1.x * y.x; a1y[m] += x1.y * y.y;
            }
        }
    }

    float contrib = 0.f;
    int ta = t0 + 2 * lane, tb = ta + 1;
#pragma unroll
    for (int rsel = 0; rsel < 2; rsel++) {
        float* vx = rsel ? a1x : a0x;
        float* vy = rsel ? a1y : a0y;
        int row = rsel ? row1 : row0;
        int pr = row ^ 8;
        float mxa = -INFINITY, mxb = -INFINITY, pa = 0.f, pb = 0.f;
#pragma unroll
        for (int m = 0; m < 16; m++) {
            if (m == pr) { pa = vx[m]; pb = vy[m]; }
            if (m != row) { mxa = fmaxf(mxa, vx[m]); mxb = fmaxf(mxb, vy[m]); }
        }
        float sa = 0.f, sb = 0.f;
#pragma unroll
        for (int m = 0; m < 16; m++) {
            if (m != row) { sa += __expf(vx[m] - mxa); sb += __expf(vy[m] - mxb); }
        }
        if (ta < T) contrib += mxa + logf(sa) - pa;
        if (tb < T) contrib += mxb + logf(sb) - pb;
    }
#pragma unroll
    for (int m = 16; m >= 1; m >>= 1)
        contrib += __shfl_xor_sync(0xffffffffu, contrib, m);
    if (lane == 0) atomicAdd(&g_acc[0], (double)contrib * scale);
}

// ---------------- temporal loss: bf16 HMMA flash-Gram ----------------
#define B_BASE   83968
#define PART_OFF 104448
#define POS_OFF  108544
#define TEMP_SMEM 109056
#define NSTAGE 10   // K=320 in chunks of 32

__device__ __forceinline__ void b_prefetch(uint32_t sb, int stage_buf, int c0, int kbase,
                                           const __nv_bfloat16* Xh, int R, int tid) {
    uint32_t bb = sb + B_BASE + stage_buf * 10240;
    for (int e = tid; e < 512; e += 256) {
        int col = e >> 2, ch = e & 3;
        int gcol = c0 + col;
        bool v = gcol < R;
        const __nv_bfloat16* src = Xh + (long)(v ? gcol : 0) * C_DIM + kbase + ch * 8;
        cpa16(bb + col * 80 + ch * 16, src, v);
    }
    CP_COMMIT();
}

__global__ void __launch_bounds__(256, 2)
temp_all_kernel(int T_start) {
    extern __shared__ char smem[];
    uint32_t sb = smem_u32(smem);
    int tid = threadIdx.x;
    int wid = tid >> 5;
    int lane = tid & 31;

    int rem = blockIdx.x;
    int T = T_start;
    int nb;
    while (true) {
        nb = (2 * T + 127) >> 7;
        if (rem < nb * 8) break;
        rem -= nb * 8;
        T >>= 1;
    }
    int b    = rem / nb;
    int tile = rem % nb;
    int R = 2 * T;
    int r0 = tile * 128;
    long xoff = 5120L * (2L * T_TOP - 2L * T);
    double scale = 1.0 / (16.0 * (double)T);
    const __nv_bfloat16* Xh = g_xhi + xoff + (long)b * R * C_DIM;

    int warp_m = (wid >> 2) * 64;
    int warp_n = (wid & 3) * 32;
    int warp_cn = wid & 3;

    for (int e = tid; e < 128 * 40; e += 256) {
        int row = e / 40;
        int ch  = e - row * 40;
        int grow = r0 + row;
        bool v = grow < R;
        const __nv_bfloat16* sh = Xh + (long)(v ? grow : 0) * C_DIM + ch * 8;
        cpa16(sb + row * 656 + ch * 16, sh, v);
    }
    b_prefetch(sb, 0, 0, 0, Xh, R, tid);

    float* poss = reinterpret_cast<float*>(smem + POS_OFF);
    if (tid < 128) poss[tid] = 0.f;

    float m_run = -INFINITY, s_run = 0.f;

    int ntiles = (R + 127) >> 7;
    for (int ct = 0; ct < ntiles; ct++) {
        int c0 = ct * 128;
        float acc[4][4][4];
#pragma unroll
        for (int mt = 0; mt < 4; mt++)
#pragma unroll
            for (int nt = 0; nt < 4; nt++)
#pragma unroll
                for (int q = 0; q < 4; q++) acc[mt][nt][q] = 0.f;

        for (int ks = 0; ks < NSTAGE; ks++) {
            CP_WAIT0();
            __syncthreads();
            if (ks + 1 < NSTAGE)
                b_prefetch(sb, (ks + 1) & 1, c0, (ks + 1) * 32, Xh, R, tid);

            uint32_t bbuf = sb + B_BASE + (ks & 1) * 10240;
            int kbase = ks * 32;
#pragma unroll
            for (int kk = 0; kk < 2; kk++) {
                int kg2 = kk * 16;
                uint32_t ah[4][4];
#pragma unroll
                for (int mt = 0; mt < 4; mt++) {
                    uint32_t addr = sb + (warp_m + mt * 16 + (lane & 15)) * 656 +
                                    (kbase + kg2) * 2 + ((lane >> 4) << 4);
                    ldmx4(ah[mt], addr);
                }
                uint32_t bh[2][4];
#pragma unroll
                for (int g = 0; g < 2; g++) {
                    uint32_t addr = bbuf + (warp_n + g * 16 + (lane & 15)) * 80 +
                                    kg2 * 2 + ((lane >> 4) << 4);
                    ldmx4(bh[g], addr);
                }
#pragma unroll
                for (int mt = 0; mt < 4; mt++)
#pragma unroll
                    for (int nt = 0; nt < 4; nt++) {
                        int g = nt >> 1, s = nt & 1;
                        mma_bf16(acc[mt][nt], ah[mt], bh[g][s], bh[g][s + 2]);
                    }
            }
        }

        if (ct + 1 < ntiles)
            b_prefetch(sb, 0, c0 + 128, 0, Xh, R, tid);

        float2* part = reinterpret_cast<float2*>(smem + PART_OFF);
#pragma unroll
        for (int mt = 0; mt < 4; mt++)
#pragma unroll
            for (int h = 0; h < 2; h++) {
                int row_local = warp_m + mt * 16 + (lane >> 2) + 8 * h;
                int grow = r0 + row_local;
                int prow = (grow < T) ? grow + T : grow - T;
                float vals[8];
                float mloc = -INFINITY;
#pragma unroll
                for (int nt = 0; nt < 4; nt++)
#pragma unroll
                    for (int e2 = 0; e2 < 2; e2++) {
                        float v = acc[mt][nt][h * 2 + e2];
                        int gcol = c0 + warp_n + nt * 8 + (lane & 3) * 2 + e2;
                        bool bad = (gcol >= R) || (gcol == grow);
                        if (!bad && gcol == prow && grow < R) poss[row_local] = v;
                        v = bad ? -INFINITY : v;
                        vals[nt * 2 + e2] = v;
                        mloc = fmaxf(mloc, v);
                    }
                float sl = 0.f;
#pragma unroll
                for (int q = 0; q < 8; q++)
                    sl += (vals[q] > -INFINITY) ? __expf(vals[q] - mloc) : 0.f;
#pragma unroll
                for (int d = 1; d < 4; d <<= 1) {
                    float mo = __shfl_xor_sync(0xffffffffu, mloc, d);
                    float so = __shfl_xor_sync(0xffffffffu, sl, d);
                    float nm = fmaxf(mloc, mo);
                    float s1v = (mloc > -INFINITY) ? sl * __expf(mloc - nm) : 0.f;
                    float s2v = (mo > -INFINITY) ? so * __expf(mo - nm) : 0.f;
                    sl = s1v + s2v;
                    mloc = nm;
                }
                if ((lane & 3) == 0)
                    part[row_local * 4 + warp_cn] = make_float2(mloc, sl);
            }
        __syncthreads();
        if (tid < 128) {
#pragma unroll
            for (int w = 0; w < 4; w++) {
                float2 p = part[tid * 4 + w];
                if (p.y > 0.f) {
                    float nm = fmaxf(m_run, p.x);
                    float s0 = (s_run > 0.f) ? s_run * __expf(m_run - nm) : 0.f;
                    s_run = s0 + p.y * __expf(p.x - nm);
                    m_run = nm;
                }
            }
        }
        __syncthreads();
    }

    float contrib = 0.f;
    if (tid < 128) {
        int grow = r0 + tid;
        if (grow < R) contrib = m_run + logf(s_run) - poss[tid];
    }
#pragma unroll
    for (int m = 16; m >= 1; m >>= 1)
        contrib += __shfl_xor_sync(0xffffffffu, contrib, m);
    if (lane == 0 && wid < 4)
        atomicAdd(&g_acc[1], (double)contrib * scale);
}

// ---------------- host ----------------
extern "C" void kernel_launch(void* const* d_in, const int* in_sizes, int n_in,
                              void* d_out, int out_size) {
    (void)in_sizes; (void)n_in; (void)out_size;
    const float* z1 = (const float*)d_in[0];
    const float* z2 = (const float*)d_in[1];
    float* out = (float*)d_out;

    float *p1 = nullptr, *p2 = nullptr;
    cudaGetSymbolAddress((void**)&p1, g_z1p);
    cudaGetSymbolAddress((void**)&p2, g_z2p);
    cudaFuncSetAttribute(temp_all_kernel,
                         cudaFuncAttributeMaxDynamicSharedMemorySize, TEMP_SMEM);

    zero_kernel<<<1, 1>>>();                               // launch 1

    dim3 cb(32, 8);
    {                                                      // launch 2
        dim3 cg((T_TOP + 31) / 32, 10, 16);
        convert_kernel<<<cg, cb>>>(z1, z2, T_TOP, 0L);
    }

    // pool+convert level 1                                // launch 3
    const float *s1 = z1, *s2 = z2;
    {
        int T = T_TOP >> 1;
        long off = (long)B_DIM * C_DIM * (T_TOP - 2 * T);
        float* d1 = p1 + off;
        float* d2p = p2 + off;
        long xoff = 5120L * (2L * T_TOP - 2L * T);
        dim3 cg((T + 31) / 32, 10, 16);
        poolconv_kernel<<<cg, cb>>>(s1, s2, d1, d2p, T, xoff);
        s1 = d1; s2 = d2p;
    }

    // temporal level 0 — launch 4 (profiled by ncu -s 5 -c 1)
    temp_all_kernel<<<256, 256, TEMP_SMEM>>>(T_TOP);

    // pool+convert levels 2..11
    for (int lvl = 2; lvl <= 11; lvl++) {
        int T = T_TOP >> lvl;
        long off = (long)B_DIM * C_DIM * (T_TOP - 2 * T);
        float* d1 = p1 + off;
        float* d2p = p2 + off;
        long xoff = 5120L * (2L * T_TOP - 2L * T);
        dim3 cg((T + 31) / 32, 10, 16);
        poolconv_kernel<<<cg, cb>>>(s1, s2, d1, d2p, T, xoff);
        s1 = d1; s2 = d2p;
    }

    // temporal levels 1..11
    {
        int nblk = 0;
        for (int lvl = 1; lvl <= 11; lvl++) {
            int T = T_TOP >> lvl;
            nblk += ((2 * T + 127) >> 7) * 8;
        }
        temp_all_kernel<<<nblk, 256, TEMP_SMEM>>>(T_TOP >> 1);
    }

    // instance loss
    {
        int nblk = 0;
        for (int lvl = 0; lvl <= 11; lvl++) nblk += ((T_TOP >> lvl) + 63) / 64;
        inst_all_kernel<<<nblk, 256>>>(z1, z2);
    }

    fin_kernel<<<1, 1>>>(out);
}

// round 9
// speedup vs baseline: 1.0837x; 1.0837x over previous
#include <cuda_runtime.h>
#include <cuda_bf16.h>
#include <cstdint>
#include <math.h>

#define C_DIM 320
#define B_DIM 8
#define T_TOP 2048
#define NDIV 11.0
#define MINF -1e30f

// ---------------- scratch ----------------
#define POOL_FLOATS (B_DIM * C_DIM * 2047)
#define X_ELEMS (B_DIM * C_DIM * 8190)
__device__ float g_z1p[POOL_FLOATS];
__device__ float g_z2p[POOL_FLOATS];
__device__ __align__(256) __nv_bfloat16 g_xhi[X_ELEMS];
__device__ double g_acc[2];   // [0]=inst, [1]=temp

// ---------------- PTX helpers (sm_80-era only) ----------------
__device__ __forceinline__ uint32_t smem_u32(const void* p) {
    uint32_t a;
    asm("{ .reg .u64 t; cvta.to.shared.u64 t, %1; cvt.u32.u64 %0, t; }" : "=r"(a) : "l"(p));
    return a;
}
__device__ __forceinline__ void ldmx4(uint32_t* r, uint32_t addr) {
    asm volatile("ldmatrix.sync.aligned.m8n8.x4.shared.b16 {%0,%1,%2,%3}, [%4];"
                 : "=r"(r[0]), "=r"(r[1]), "=r"(r[2]), "=r"(r[3]) : "r"(addr));
}
__device__ __forceinline__ void mma_bf16(float* c, const uint32_t* a,
                                         uint32_t b0, uint32_t b1) {
    asm volatile("mma.sync.aligned.m16n8k16.row.col.f32.bf16.bf16.f32 "
                 "{%0,%1,%2,%3}, {%4,%5,%6,%7}, {%8,%9}, {%0,%1,%2,%3};"
                 : "+f"(c[0]), "+f"(c[1]), "+f"(c[2]), "+f"(c[3])
                 : "r"(a[0]), "r"(a[1]), "r"(a[2]), "r"(a[3]), "r"(b0), "r"(b1));
}
__device__ __forceinline__ void cpa16(uint32_t dst, const void* src, bool valid) {
    int sz = valid ? 16 : 0;
    asm volatile("cp.async.cg.shared.global [%0], [%1], 16, %2;"
                 :: "r"(dst), "l"(src), "r"(sz));
}
#define CP_COMMIT() asm volatile("cp.async.commit_group;" ::: "memory")
#define CP_WAIT0()  asm volatile("cp.async.wait_group 0;" ::: "memory")

// ---------------- trivial kernels ----------------
__global__ void zero_kernel() { g_acc[0] = 0.0; g_acc[1] = 0.0; }

__global__ void fin_kernel(float* out) {
    double inst = g_acc[0] / NDIV;
    double temp = g_acc[1] / NDIV;
    out[0] = (float)(0.5 * inst + 0.5 * temp);
    out[1] = (float)inst;
    out[2] = (float)temp;
}

// convert level-0 to bf16, layout [b][row(2T)][c]
__global__ void convert_kernel(const float* __restrict__ z1, const float* __restrict__ z2,
                               int T, long xoff) {
    __shared__ float tile[32][33];
    int zsel = blockIdx.z & 1;
    int b = blockIdx.z >> 1;
    const float* src = (zsel ? z2 : z1) + (long)b * C_DIM * T;
    int t0 = blockIdx.x * 32, c0 = blockIdx.y * 32;
    int tx = threadIdx.x, ty = threadIdx.y;   // 32 x 8
#pragma unroll
    for (int j = 0; j < 4; j++) {
        int c = c0 + ty + 8 * j;
        int t = t0 + tx;
        tile[ty + 8 * j][tx] = (t < T) ? src[(long)c * T + t] : 0.f;
    }
    __syncthreads();
    long R = 2L * T;
#pragma unroll
    for (int j = 0; j < 4; j++) {
        int row = t0 + ty + 8 * j;
        int c = c0 + tx;
        if (row < T) {
            float x = tile[tx][ty + 8 * j];
            long grow = zsel ? (T + row) : row;
            g_xhi[xoff + ((long)b * R + grow) * C_DIM + c] = __float2bfloat16(x);
        }
    }
}

// fused pool (2:1 max) + convert for levels >= 1
__global__ void poolconv_kernel(const float* __restrict__ s1, const float* __restrict__ s2,
                                float* __restrict__ d1, float* __restrict__ d2,
                                int T, long xoff) {
    __shared__ float tile[32][33];
    int zsel = blockIdx.z & 1;
    int b = blockIdx.z >> 1;
    int Tin = 2 * T;
    const float* src = (zsel ? s2 : s1) + (long)b * C_DIM * Tin;
    float* dst = (zsel ? d2 : d1) + (long)b * C_DIM * T;
    int t0 = blockIdx.x * 32, c0 = blockIdx.y * 32;
    int tx = threadIdx.x, ty = threadIdx.y;
#pragma unroll
    for (int j = 0; j < 4; j++) {
        int c = c0 + ty + 8 * j;
        int t = t0 + tx;
        float v = 0.f;
        if (t < T) {
            v = fmaxf(src[(long)c * Tin + 2 * t], src[(long)c * Tin + 2 * t + 1]);
            dst[(long)c * T + t] = v;
        }
        tile[ty + 8 * j][tx] = v;
    }
    __syncthreads();
    long R = 2L * T;
#pragma unroll
    for (int j = 0; j < 4; j++) {
        int row = t0 + ty + 8 * j;
        int c = c0 + tx;
        if (row < T) {
            float x = tile[tx][ty + 8 * j];
            long grow = zsel ? (T + row) : row;
            g_xhi[xoff + ((long)b * R + grow) * C_DIM + c] = __float2bfloat16(x);
        }
    }
}

// ---------------- instance loss, all levels in one launch ----------------
__global__ void inst_all_kernel(const float* __restrict__ z1, const float* __restrict__ z2) {
    __shared__ float sm[16][8][64];
    int rem = blockIdx.x;
    int T = T_TOP;
    int lvl = 0;
    while (true) {
        int nb = (T + 63) >> 6;
        if (rem < nb) break;
        rem -= nb;
        T >>= 1;
        lvl++;
    }
    const float *s1, *s2;
    if (lvl == 0) { s1 = z1; s2 = z2; }
    else {
        long off = (long)B_DIM * C_DIM * (T_TOP - 2 * T);
        s1 = g_z1p + off; s2 = g_z2p + off;
    }
    double scale = 1.0 / (16.0 * (double)T);

    int tid  = threadIdx.x;
    int lane = tid & 31;
    int grp  = tid >> 5;
    int t0   = rem * 64;
    int row0 = grp * 2, row1 = row0 + 1;

    float a0x[16], a0y[16], a1x[16], a1y[16];
#pragma unroll
    for (int m = 0; m < 16; m++) { a0x[m] = a0y[m] = a1x[m] = a1y[m] = 0.f; }

    for (int cc = 0; cc < C_DIM; cc += 8) {
        __syncthreads();
        for (int e = tid; e < 16 * 8 * 64; e += 256) {
            int t = e & 63, c = (e >> 6) & 7, v = e >> 9;
            int gt = t0 + t;
            float val = 0.f;
            if (gt < T) {
                int gc = cc + c;
                val = (v < 8) ? s1[((long)v * C_DIM + gc) * T + gt]
                              : s2[((long)(v - 8) * C_DIM + gc) * T + gt];
            }
            sm[v][c][t] = val;
        }
        __syncthreads();
#pragma unroll
        for (int c = 0; c < 8; c++) {
            float2 x0 = *reinterpret_cast<const float2*>(&sm[row0][c][2 * lane]);
            float2 x1 = *reinterpret_cast<const float2*>(&sm[row1][c][2 * lane]);
#pragma unroll
            for (int m = 0; m < 16; m++) {
                float2 y = *reinterpret_cast<const float2*>(&sm[m][c][2 * lane]);
                a0x[m] += x0.x * y.x; a0y[m] += x0.y * y.y;
                a1x[m] += x1.x * y.x; a1y[m] += x1.y * y.y;
            }
        }
    }

    float contrib = 0.f;
    int ta = t0 + 2 * lane, tb = ta + 1;
#pragma unroll
    for (int rsel = 0; rsel < 2; rsel++) {
        float* vx = rsel ? a1x : a0x;
        float* vy = rsel ? a1y : a0y;
        int row = rsel ? row1 : row0;
        int pr = row ^ 8;
        float mxa = MINF, mxb = MINF, pa = 0.f, pb = 0.f;
#pragma unroll
        for (int m = 0; m < 16; m++) {
            if (m == pr) { pa = vx[m]; pb = vy[m]; }
            if (m != row) { mxa = fmaxf(mxa, vx[m]); mxb = fmaxf(mxb, vy[m]); }
        }
        float sa = 0.f, sb = 0.f;
#pragma unroll
        for (int m = 0; m < 16; m++) {
            if (m != row) { sa += __expf(vx[m] - mxa); sb += __expf(vy[m] - mxb); }
        }
        if (ta < T) contrib += mxa + logf(sa) - pa;
        if (tb < T) contrib += mxb + logf(sb) - pb;
    }
#pragma unroll
    for (int m = 16; m >= 1; m >>= 1)
        contrib += __shfl_xor_sync(0xffffffffu, contrib, m);
    if (lane == 0) atomicAdd(&g_acc[0], (double)contrib * scale);
}

// ---------------- temporal loss: bf16 HMMA flash-Gram, all levels fused ----------------
#define B_BASE   83968
#define PART_OFF 104448
#define POS_OFF  108544
#define TEMP_SMEM 109056
#define NSTAGE 10   // K=320 in chunks of 32

__device__ __forceinline__ void b_prefetch(uint32_t sb, int stage_buf, int c0, int kbase,
                                           const __nv_bfloat16* Xh, int R, int tid) {
    uint32_t bb = sb + B_BASE + stage_buf * 10240;
    for (int e = tid; e < 512; e += 256) {
        int col = e >> 2, ch = e & 3;
        int gcol = c0 + col;
        bool v = gcol < R;
        const __nv_bfloat16* src = Xh + (long)(v ? gcol : 0) * C_DIM + kbase + ch * 8;
        cpa16(bb + col * 80 + ch * 16, src, v);
    }
    CP_COMMIT();
}

__global__ void __launch_bounds__(256, 2)
temp_all_kernel(int T_start) {
    extern __shared__ char smem[];
    uint32_t sb = smem_u32(smem);
    int tid = threadIdx.x;
    int wid = tid >> 5;
    int lane = tid & 31;

    int rem = blockIdx.x;
    int T = T_start;
    int nb;
    while (true) {
        nb = (2 * T + 127) >> 7;
        if (rem < nb * 8) break;
        rem -= nb * 8;
        T >>= 1;
    }
    int b    = rem / nb;
    int tile = rem % nb;
    int R = 2 * T;
    int r0 = tile * 128;
    long xoff = 5120L * (2L * T_TOP - 2L * T);
    double scale = 1.0 / (16.0 * (double)T);
    const __nv_bfloat16* Xh = g_xhi + xoff + (long)b * R * C_DIM;

    int warp_m = (wid >> 2) * 64;
    int warp_n = (wid & 3) * 32;
    int warp_cn = wid & 3;

    for (int e = tid; e < 128 * 40; e += 256) {
        int row = e / 40;
        int ch  = e - row * 40;
        int grow = r0 + row;
        bool v = grow < R;
        const __nv_bfloat16* sh = Xh + (long)(v ? grow : 0) * C_DIM + ch * 8;
        cpa16(sb + row * 656 + ch * 16, sh, v);
    }
    b_prefetch(sb, 0, 0, 0, Xh, R, tid);

    float* poss = reinterpret_cast<float*>(smem + POS_OFF);
    if (tid < 128) poss[tid] = 0.f;

    // per-thread running lse state for the 8 owned row-slots
    float m_r[8], s_r[8];
#pragma unroll
    for (int i = 0; i < 8; i++) { m_r[i] = MINF; s_r[i] = 0.f; }

    int ntiles = (R + 127) >> 7;
    for (int ct = 0; ct < ntiles; ct++) {
        int c0 = ct * 128;
        float acc[4][4][4];
#pragma unroll
        for (int mt = 0; mt < 4; mt++)
#pragma unroll
            for (int nt = 0; nt < 4; nt++)
#pragma unroll
                for (int q = 0; q < 4; q++) acc[mt][nt][q] = 0.f;

        for (int ks = 0; ks < NSTAGE; ks++) {
            CP_WAIT0();
            __syncthreads();
            if (ks + 1 < NSTAGE)
                b_prefetch(sb, (ks + 1) & 1, c0, (ks + 1) * 32, Xh, R, tid);

            uint32_t bbuf = sb + B_BASE + (ks & 1) * 10240;
            int kbase = ks * 32;
#pragma unroll
            for (int kk = 0; kk < 2; kk++) {
                int kg2 = kk * 16;
                uint32_t ah[4][4];
#pragma unroll
                for (int mt = 0; mt < 4; mt++) {
                    uint32_t addr = sb + (warp_m + mt * 16 + (lane & 15)) * 656 +
                                    (kbase + kg2) * 2 + ((lane >> 4) << 4);
                    ldmx4(ah[mt], addr);
                }
                uint32_t bh[2][4];
#pragma unroll
                for (int g = 0; g < 2; g++) {
                    uint32_t addr = bbuf + (warp_n + g * 16 + (lane & 15)) * 80 +
                                    kg2 * 2 + ((lane >> 4) << 4);
                    ldmx4(bh[g], addr);
                }
#pragma unroll
                for (int mt = 0; mt < 4; mt++)
#pragma unroll
                    for (int nt = 0; nt < 4; nt++) {
                        int g = nt >> 1, s = nt & 1;
                        mma_bf16(acc[mt][nt], ah[mt], bh[g][s], bh[g][s + 2]);
                    }
            }
        }

        if (ct + 1 < ntiles)
            b_prefetch(sb, 0, c0 + 128, 0, Xh, R, tid);

        // ---- register-only epilogue: no syncs, no shuffles ----
#pragma unroll
        for (int mt = 0; mt < 4; mt++)
#pragma unroll
            for (int h = 0; h < 2; h++) {
                int idx = mt * 2 + h;
                int row_local = warp_m + mt * 16 + (lane >> 2) + 8 * h;
                int grow = r0 + row_local;
                int prow = (grow < T) ? grow + T : grow - T;
                float vals[8];
                float mloc = MINF;
#pragma unroll
                for (int nt = 0; nt < 4; nt++)
#pragma unroll
                    for (int e2 = 0; e2 < 2; e2++) {
                        float v = acc[mt][nt][h * 2 + e2];
                        int gcol = c0 + warp_n + nt * 8 + (lane & 3) * 2 + e2;
                        bool bad = (gcol >= R) || (gcol == grow);
                        if (!bad && gcol == prow) poss[row_local] = v;
                        v = bad ? MINF : v;
                        vals[nt * 2 + e2] = v;
                        mloc = fmaxf(mloc, v);
                    }
                if (mloc > -1e29f) {
                    float nm = fmaxf(m_r[idx], mloc);
                    float st = 0.f;
#pragma unroll
                    for (int q = 0; q < 8; q++) st += __expf(vals[q] - nm);
                    s_r[idx] = s_r[idx] * __expf(m_r[idx] - nm) + st;
                    m_r[idx] = nm;
                }
            }
    }

    // ---- single final merge ----
    float2* part = reinterpret_cast<float2*>(smem + PART_OFF);
#pragma unroll
    for (int idx = 0; idx < 8; idx++) {
        float m = m_r[idx], s = s_r[idx];
#pragma unroll
        for (int d = 1; d < 4; d <<= 1) {
            float mo = __shfl_xor_sync(0xffffffffu, m, d);
            float so = __shfl_xor_sync(0xffffffffu, s, d);
            float nm = fmaxf(m, mo);
            s = s * __expf(m - nm) + so * __expf(mo - nm);
            m = nm;
        }
        if ((lane & 3) == 0) {
            int mt = idx >> 1, h = idx & 1;
            int row_local = warp_m + mt * 16 + (lane >> 2) + 8 * h;
            part[row_local * 4 + warp_cn] = make_float2(m, s);
        }
    }
    __syncthreads();

    float contrib = 0.f;
    if (tid < 128) {
        int grow = r0 + tid;
        if (grow < R) {
            float m = MINF, s = 0.f;
#pragma unroll
            for (int w = 0; w < 4; w++) {
                float2 p = part[tid * 4 + w];
                float nm = fmaxf(m, p.x);
                s = s * __expf(m - nm) + p.y * __expf(p.x - nm);
                m = nm;
            }
            contrib = m + logf(s) - poss[tid];
        }
    }
#pragma unroll
    for (int m = 16; m >= 1; m >>= 1)
        contrib += __shfl_xor_sync(0xffffffffu, contrib, m);
    if (lane == 0 && wid < 4)
        atomicAdd(&g_acc[1], (double)contrib * scale);
}

// ---------------- host ----------------
extern "C" void kernel_launch(void* const* d_in, const int* in_sizes, int n_in,
                              void* d_out, int out_size) {
    (void)in_sizes; (void)n_in; (void)out_size;
    const float* z1 = (const float*)d_in[0];
    const float* z2 = (const float*)d_in[1];
    float* out = (float*)d_out;

    float *p1 = nullptr, *p2 = nullptr;
    cudaGetSymbolAddress((void**)&p1, g_z1p);
    cudaGetSymbolAddress((void**)&p2, g_z2p);
    cudaFuncSetAttribute(temp_all_kernel,
                         cudaFuncAttributeMaxDynamicSharedMemorySize, TEMP_SMEM);

    zero_kernel<<<1, 1>>>();

    dim3 cb(32, 8);
    {
        dim3 cg((T_TOP + 31) / 32, 10, 16);
        convert_kernel<<<cg, cb>>>(z1, z2, T_TOP, 0L);
    }

    const float *s1 = z1, *s2 = z2;
    for (int lvl = 1; lvl <= 11; lvl++) {
        int T = T_TOP >> lvl;
        long off = (long)B_DIM * C_DIM * (T_TOP - 2 * T);
        float* d1 = p1 + off;
        float* d2p = p2 + off;
        long xoff = 5120L * (2L * T_TOP - 2L * T);
        dim3 cg((T + 31) / 32, 10, 16);
        poolconv_kernel<<<cg, cb>>>(s1, s2, d1, d2p, T, xoff);
        s1 = d1; s2 = d2p;
    }

    // temporal loss: one fused launch, levels 0..11 (552 CTAs)
    {
        int nblk = 0;
        for (int lvl = 0; lvl <= 11; lvl++) {
            int T = T_TOP >> lvl;
            nblk += ((2 * T + 127) >> 7) * 8;
        }
        temp_all_kernel<<<nblk, 256, TEMP_SMEM>>>(T_TOP);
    }

    // instance loss: one launch
    {
        int nblk = 0;
        for (int lvl = 0; lvl <= 11; lvl++) nblk += ((T_TOP >> lvl) + 63) / 64;
        inst_all_kernel<<<nblk, 256>>>(z1, z2);
    }

    fin_kernel<<<1, 1>>>(out);
}